// round 12
// baseline (speedup 1.0000x reference)
#include <cuda_runtime.h>
#include <cuda_fp16.h>
#include <cuda_bf16.h>
#include <cstdint>

// Problem constants
#define BB 8
#define QQ 128
#define KK 512
#define DD 256
#define UU 256
#define TQ 8               // q rows per score block
#define KC 32              // k rows per score block
#define TQO 4              // q rows per softout block

// Scratch (static device arrays: no allocation)
__device__ float g_qp[BB * QQ * UU];   // 1 MB
__device__ float g_kp[BB * KK * UU];   // 4 MB
__device__ float g_sc[BB * QQ * KK];   // 2 MB raw scores

// two tanhs per MUFU op
__device__ __forceinline__ __half2 tanh2_approx(__half2 x) {
    uint32_t xi = *(uint32_t*)&x, yi;
    asm("tanh.approx.f16x2 %0, %1;" : "=r"(yi) : "r"(xi));
    return *(__half2*)&yi;
}

__device__ __forceinline__ void cp_async16(uint32_t smem, const void* g) {
    asm volatile("cp.async.cg.shared.global [%0], [%1], 16;\n" :: "r"(smem), "l"(g));
}
__device__ __forceinline__ void cp_commit() { asm volatile("cp.async.commit_group;\n"); }
template <int N>
__device__ __forceinline__ void cp_wait() { asm volatile("cp.async.wait_group %0;\n" :: "n"(N)); }

// ---------------------------------------------------------------------------
// Merged projection GEMM (R8 config — best measured): rows [0,1024) =
// query@Wq -> g_qp ; rows [1024,5120) = key@Wk -> g_kp.
// BM=64, BN=64, BK=16, 128 threads, 8x4 per-thread tile, reg-prefetch.
// ---------------------------------------------------------------------------
__global__ __launch_bounds__(128) void proj_gemm(const float* __restrict__ query,
                                                 const float* __restrict__ key,
                                                 const float* __restrict__ Wq,
                                                 const float* __restrict__ Wk) {
    __shared__ float As[16][68];
    __shared__ float Ws[16][64];

    const int tid = threadIdx.x;
    const int m0  = blockIdx.y * 64;
    const int n0  = blockIdx.x * 64;

    const float* A; const float* W; float* C;
    if (m0 < BB * QQ) { A = query + (size_t)m0 * DD;             W = Wq; C = g_qp + (size_t)m0 * UU; }
    else              { A = key   + (size_t)(m0 - BB * QQ) * DD; W = Wk; C = g_kp + (size_t)(m0 - BB * QQ) * UU; }

    const int ty = tid >> 4;
    const int tx = tid & 15;
    const int ar0 = tid >> 2;
    const int ac  = (tid & 3) * 4;
    const int wr0 = tid >> 4;
    const int wc  = (tid & 15) * 4;

    float acc[8][4];
#pragma unroll
    for (int i = 0; i < 8; i++)
#pragma unroll
        for (int j = 0; j < 4; j++) acc[i][j] = 0.0f;

    // preload slab 0
    float4 a0 = *(const float4*)&A[(ar0)      * DD + ac];
    float4 a1 = *(const float4*)&A[(ar0 + 32) * DD + ac];
    float4 w0 = *(const float4*)&W[(wr0)     * UU + n0 + wc];
    float4 w1 = *(const float4*)&W[(wr0 + 8) * UU + n0 + wc];

    for (int k0 = 0; k0 < DD; k0 += 16) {
        __syncthreads();
        As[ac + 0][ar0] = a0.x; As[ac + 1][ar0] = a0.y;
        As[ac + 2][ar0] = a0.z; As[ac + 3][ar0] = a0.w;
        As[ac + 0][ar0 + 32] = a1.x; As[ac + 1][ar0 + 32] = a1.y;
        As[ac + 2][ar0 + 32] = a1.z; As[ac + 3][ar0 + 32] = a1.w;
        *(float4*)&Ws[wr0][wc]     = w0;
        *(float4*)&Ws[wr0 + 8][wc] = w1;
        __syncthreads();
        if (k0 + 16 < DD) {
            a0 = *(const float4*)&A[(ar0)      * DD + k0 + 16 + ac];
            a1 = *(const float4*)&A[(ar0 + 32) * DD + k0 + 16 + ac];
            w0 = *(const float4*)&W[(k0 + 16 + wr0)     * UU + n0 + wc];
            w1 = *(const float4*)&W[(k0 + 16 + wr0 + 8) * UU + n0 + wc];
        }
#pragma unroll
        for (int kk = 0; kk < 16; kk++) {
            float4 av0 = *(const float4*)&As[kk][ty * 8];
            float4 av1 = *(const float4*)&As[kk][ty * 8 + 4];
            float4 wv  = *(const float4*)&Ws[kk][tx * 4];
            float am[8] = {av0.x, av0.y, av0.z, av0.w, av1.x, av1.y, av1.z, av1.w};
            float wn[4] = {wv.x, wv.y, wv.z, wv.w};
#pragma unroll
            for (int i = 0; i < 8; i++)
#pragma unroll
                for (int j = 0; j < 4; j++)
                    acc[i][j] = fmaf(am[i], wn[j], acc[i][j]);
        }
    }
#pragma unroll
    for (int i = 0; i < 8; i++) {
        float4 o = make_float4(acc[i][0], acc[i][1], acc[i][2], acc[i][3]);
        *(float4*)&C[(size_t)(ty * 8 + i) * UU + n0 + tx * 4] = o;
    }
}

// ---------------------------------------------------------------------------
// Score kernel (f16x2 tanh): block per (chunk, qtile of 8, b). 256 thr.
// Warp w owns u4-range [8w, 8w+8); lane l = k-row. Args computed in f32,
// packed to half2, one tanh.approx.f16x2 per pair, f32 FFMA accumulate.
// ---------------------------------------------------------------------------
__global__ __launch_bounds__(256, 4) void score_kernel(const int* __restrict__ valid_len,
                                                       const float* __restrict__ v_w) {
    __shared__ float4 kb[KC * 64];        // 32KB swizzled kp chunk
    __shared__ float  qp_s[TQ * UU];      // 8KB
    __shared__ float  vw_s[UU];           // 1KB
    __shared__ float  part[8][TQ][32];    // 8KB u-partials

    const int b  = blockIdx.z;
    const int vl = __ldg(&valid_len[b]);
    const int k0 = blockIdx.x * KC;
    if (k0 >= vl) return;

    const int tid = threadIdx.x;
    const int q0  = blockIdx.y * TQ;

    {
        const float4* qg = (const float4*)(g_qp + (size_t)(b * QQ + q0) * UU);
        ((float4*)qp_s)[tid]       = qg[tid];
        ((float4*)qp_s)[tid + 256] = qg[tid + 256];
        if (tid < 64) ((float4*)vw_s)[tid] = ((const float4*)v_w)[tid];
    }

    const float4* src = (const float4*)(g_kp + ((size_t)b * KK + k0) * UU);
    const uint32_t kb_base = (uint32_t)__cvta_generic_to_shared(kb);
#pragma unroll
    for (int i = 0; i < 8; i++) {
        int idx = tid + i * 256;
        int rr = idx >> 6, cc = idx & 63;
        cp_async16(kb_base + ((uint32_t)(rr * 64 + (cc ^ (rr & 7))) << 4), src + idx);
    }
    cp_commit();
    cp_wait<0>();
    __syncthreads();

    const int w = tid >> 5, l = tid & 31;
    const float4* kbuf = kb + l * 64;
    const float4* qp4  = (const float4*)qp_s;
    const float4* vw4  = (const float4*)vw_s;
    const int u0  = w * 8;
    const int swl = l & 7;

    float acc[TQ];
#pragma unroll
    for (int r = 0; r < TQ; r++) acc[r] = 0.0f;

#pragma unroll
    for (int j = 0; j < 8; j++) {
        const int u4 = u0 + j;
        float4 k4 = kbuf[u4 ^ swl];        // spread, conflict-free
        float4 vv = vw4[u4];               // uniform broadcast
#pragma unroll
        for (int r = 0; r < TQ; r++) {
            float4 q = qp4[r * 64 + u4];   // uniform broadcast
            __half2 h0 = __floats2half2_rn(q.x + k4.x, q.y + k4.y);
            __half2 h1 = __floats2half2_rn(q.z + k4.z, q.w + k4.w);
            float2 t0 = __half22float2(tanh2_approx(h0));
            float2 t1 = __half22float2(tanh2_approx(h1));
            acc[r] = fmaf(vv.x, t0.x,
                     fmaf(vv.y, t0.y,
                     fmaf(vv.z, t1.x,
                     fmaf(vv.w, t1.y, acc[r]))));
        }
    }
#pragma unroll
    for (int r = 0; r < TQ; r++) part[w][r][l] = acc[r];
    __syncthreads();

    {   // 256 threads = 8 rows x 32 lanes: reduce over 8 warps and store
        const int r = tid >> 5, ll = tid & 31;
        float s = 0.f;
#pragma unroll
        for (int ww = 0; ww < 8; ww++) s += part[ww][r][ll];
        g_sc[(size_t)(b * QQ + q0 + r) * KK + k0 + ll] = s;
    }
}

// ---------------------------------------------------------------------------
// Softmax + output, d-split: block = (qtile, b, d-half). 128 threads.
// ---------------------------------------------------------------------------
__global__ __launch_bounds__(128) void softout_kernel(const float* __restrict__ value,
                                                      const int* __restrict__ valid_len,
                                                      float* __restrict__ out) {
    __shared__ float sc[TQO * KK];         // 8KB normalized attn

    const int tid = threadIdx.x;
    const int b   = blockIdx.y;
    const int q0  = blockIdx.x * TQO;
    const int dh  = blockIdx.z * 128;
    const int vl  = __ldg(&valid_len[b]);
    const int w = tid >> 5, l = tid & 31;

    {   // warp w: softmax of row w
        const float* row = g_sc + (size_t)(b * QQ + q0 + w) * KK;
        float vals[16];
        float m = -3.0e38f;
#pragma unroll
        for (int i = 0; i < 16; i++) {
            int k = l + 32 * i;
            float s = (k < vl) ? __ldg(&row[k]) : -1e6f;
            vals[i] = s;
            m = fmaxf(m, s);
        }
#pragma unroll
        for (int off = 16; off; off >>= 1) m = fmaxf(m, __shfl_xor_sync(0xffffffffu, m, off));
        float ssum = 0.0f;
#pragma unroll
        for (int i = 0; i < 16; i++) {
            float e = __expf(vals[i] - m);
            vals[i] = e;
            ssum += e;
        }
#pragma unroll
        for (int off = 16; off; off >>= 1) ssum += __shfl_xor_sync(0xffffffffu, ssum, off);
        float inv = 1.0f / ssum;
#pragma unroll
        for (int i = 0; i < 16; i++) sc[w * KK + l + 32 * i] = vals[i] * inv;
    }
    __syncthreads();

    const int d = dh + tid;
    float oacc[TQO];
#pragma unroll
    for (int q = 0; q < TQO; q++) oacc[q] = 0.0f;
    const float* vb = value + (size_t)b * KK * DD;
    const int kend = (vl + 3) & ~3;
#pragma unroll 2
    for (int k = 0; k < kend; k += 4) {
        float v0 = vb[(k + 0) * DD + d];
        float v1 = vb[(k + 1) * DD + d];
        float v2 = vb[(k + 2) * DD + d];
        float v3 = vb[(k + 3) * DD + d];
#pragma unroll
        for (int q = 0; q < TQO; q++) {
            float4 a = *(const float4*)&sc[q * KK + k];
            oacc[q] = fmaf(a.x, v0, fmaf(a.y, v1, fmaf(a.z, v2, fmaf(a.w, v3, oacc[q]))));
        }
    }
    float* ob = out + (size_t)(b * QQ + q0) * DD + d;
#pragma unroll
    for (int q = 0; q < TQO; q++) ob[q * DD] = oacc[q];
}

// ---------------------------------------------------------------------------
// Launch
// ---------------------------------------------------------------------------
extern "C" void kernel_launch(void* const* d_in, const int* in_sizes, int n_in,
                              void* d_out, int out_size) {
    const float* query     = (const float*)d_in[0];
    const float* key       = (const float*)d_in[1];
    const float* value     = (const float*)d_in[2];
    const int*   valid_len = (const int*)d_in[3];
    const float* Wq        = (const float*)d_in[4];
    const float* Wk        = (const float*)d_in[5];
    const float* v_w       = (const float*)d_in[6];
    float* out = (float*)d_out;

    proj_gemm<<<dim3(UU / 64, (BB * QQ + BB * KK) / 64), 128>>>(query, key, Wq, Wk);
    score_kernel<<<dim3(KK / KC, QQ / TQ, BB), 256>>>(valid_len, v_w);
    softout_kernel<<<dim3(QQ / TQO, BB, DD / 128), 128>>>(value, valid_len, out);
}

// round 13
// speedup vs baseline: 1.0743x; 1.0743x over previous
#include <cuda_runtime.h>
#include <cuda_bf16.h>
#include <cstdint>

// Problem constants
#define BB 8
#define QQ 128
#define KK 512
#define DD 256
#define UU 256
#define TQ 8               // q rows per score block
#define KC 32              // k rows per score block
#define TQO 4              // q rows per softout block

// Scratch (static device arrays: no allocation)
__device__ float g_qp[BB * QQ * UU];   // 1 MB
__device__ float g_kp[BB * KK * UU];   // 4 MB
__device__ float g_sc[BB * QQ * KK];   // 2 MB raw scores

__device__ __forceinline__ float tanh_approx(float x) {
    float y;
    asm("tanh.approx.f32 %0, %1;" : "=f"(y) : "f"(x));
    return y;
}

__device__ __forceinline__ void cp_async16(uint32_t smem, const void* g) {
    asm volatile("cp.async.cg.shared.global [%0], [%1], 16;\n" :: "r"(smem), "l"(g));
}
__device__ __forceinline__ void cp_commit() { asm volatile("cp.async.commit_group;\n"); }
template <int N>
__device__ __forceinline__ void cp_wait() { asm volatile("cp.async.wait_group %0;\n" :: "n"(N)); }

// ---------------------------------------------------------------------------
// Merged projection GEMM, fine-grained tiles for full-chip occupancy:
// BM=32, BN=64, BK=16, 128 threads, 4x4 per-thread tile.
// Grid = 160 row-tiles x 4 col-tiles = 640 blocks -> ~10 resident blocks/SM,
// one continuous wave (no 24-block tail wave).
// rows [0,1024) = query@Wq -> g_qp ; rows [1024,5120) = key@Wk -> g_kp.
// ---------------------------------------------------------------------------
__global__ __launch_bounds__(128) void proj_gemm(const float* __restrict__ query,
                                                 const float* __restrict__ key,
                                                 const float* __restrict__ Wq,
                                                 const float* __restrict__ Wk) {
    __shared__ float As[16][36];   // transposed A tile (32 + 4 pad)
    __shared__ float Ws[16][64];

    const int tid = threadIdx.x;
    const int m0  = blockIdx.y * 32;
    const int n0  = blockIdx.x * 64;

    const float* A; const float* W; float* C;
    if (m0 < BB * QQ) { A = query + (size_t)m0 * DD;             W = Wq; C = g_qp + (size_t)m0 * UU; }
    else              { A = key   + (size_t)(m0 - BB * QQ) * DD; W = Wk; C = g_kp + (size_t)(m0 - BB * QQ) * UU; }

    const int ty = tid >> 4;            // 0..7  -> 4 output rows each (rows 0..31)
    const int tx = tid & 15;            // 0..15 -> 4 output cols each
    const int ar0 = tid >> 2;           // 0..31  A row
    const int ac  = (tid & 3) * 4;      // A col base within 16-k slab
    const int wr0 = tid >> 4;           // 0..7   W row (second row +8)
    const int wc  = (tid & 15) * 4;     // W col base

    float acc[4][4];
#pragma unroll
    for (int i = 0; i < 4; i++)
#pragma unroll
        for (int j = 0; j < 4; j++) acc[i][j] = 0.0f;

    // preload slab 0
    float4 a0 = *(const float4*)&A[ar0 * DD + ac];
    float4 w0 = *(const float4*)&W[(wr0)     * UU + n0 + wc];
    float4 w1 = *(const float4*)&W[(wr0 + 8) * UU + n0 + wc];

    for (int k0 = 0; k0 < DD; k0 += 16) {
        __syncthreads();
        As[ac + 0][ar0] = a0.x; As[ac + 1][ar0] = a0.y;
        As[ac + 2][ar0] = a0.z; As[ac + 3][ar0] = a0.w;
        *(float4*)&Ws[wr0][wc]     = w0;
        *(float4*)&Ws[wr0 + 8][wc] = w1;
        __syncthreads();
        if (k0 + 16 < DD) {   // prefetch next slab under compute
            a0 = *(const float4*)&A[ar0 * DD + k0 + 16 + ac];
            w0 = *(const float4*)&W[(k0 + 16 + wr0)     * UU + n0 + wc];
            w1 = *(const float4*)&W[(k0 + 16 + wr0 + 8) * UU + n0 + wc];
        }
#pragma unroll
        for (int kk = 0; kk < 16; kk++) {
            float4 av = *(const float4*)&As[kk][ty * 4];
            float4 wv = *(const float4*)&Ws[kk][tx * 4];
            float am[4] = {av.x, av.y, av.z, av.w};
            float wn[4] = {wv.x, wv.y, wv.z, wv.w};
#pragma unroll
            for (int i = 0; i < 4; i++)
#pragma unroll
                for (int j = 0; j < 4; j++)
                    acc[i][j] = fmaf(am[i], wn[j], acc[i][j]);
        }
    }
#pragma unroll
    for (int i = 0; i < 4; i++) {
        float4 o = make_float4(acc[i][0], acc[i][1], acc[i][2], acc[i][3]);
        *(float4*)&C[(size_t)(ty * 4 + i) * UU + n0 + tx * 4] = o;
    }
}

// ---------------------------------------------------------------------------
// Score kernel (R8 config, f32 tanh): block per (chunk, qtile of 8, b).
// 256 thr; warp w owns u4-range [8w,8w+8); lane l = k-row. q/vw loads are
// warp-uniform broadcasts; k float4 loaded once per warp per u4.
// ---------------------------------------------------------------------------
__global__ __launch_bounds__(256, 4) void score_kernel(const int* __restrict__ valid_len,
                                                       const float* __restrict__ v_w) {
    __shared__ float4 kb[KC * 64];        // 32KB swizzled kp chunk
    __shared__ float  qp_s[TQ * UU];      // 8KB
    __shared__ float  vw_s[UU];           // 1KB
    __shared__ float  part[8][TQ][32];    // 8KB u-partials

    const int b  = blockIdx.z;
    const int vl = __ldg(&valid_len[b]);
    const int k0 = blockIdx.x * KC;
    if (k0 >= vl) return;

    const int tid = threadIdx.x;
    const int q0  = blockIdx.y * TQ;

    {
        const float4* qg = (const float4*)(g_qp + (size_t)(b * QQ + q0) * UU);
        ((float4*)qp_s)[tid]       = qg[tid];
        ((float4*)qp_s)[tid + 256] = qg[tid + 256];
        if (tid < 64) ((float4*)vw_s)[tid] = ((const float4*)v_w)[tid];
    }

    const float4* src = (const float4*)(g_kp + ((size_t)b * KK + k0) * UU);
    const uint32_t kb_base = (uint32_t)__cvta_generic_to_shared(kb);
#pragma unroll
    for (int i = 0; i < 8; i++) {
        int idx = tid + i * 256;
        int rr = idx >> 6, cc = idx & 63;
        cp_async16(kb_base + ((uint32_t)(rr * 64 + (cc ^ (rr & 7))) << 4), src + idx);
    }
    cp_commit();
    cp_wait<0>();
    __syncthreads();

    const int w = tid >> 5, l = tid & 31;
    const float4* kbuf = kb + l * 64;
    const float4* qp4  = (const float4*)qp_s;
    const float4* vw4  = (const float4*)vw_s;
    const int u0  = w * 8;
    const int swl = l & 7;

    float acc[TQ];
#pragma unroll
    for (int r = 0; r < TQ; r++) acc[r] = 0.0f;

#pragma unroll
    for (int j = 0; j < 8; j++) {
        const int u4 = u0 + j;
        float4 k4 = kbuf[u4 ^ swl];        // spread, conflict-free
        float4 vv = vw4[u4];               // uniform broadcast
#pragma unroll
        for (int r = 0; r < TQ; r++) {
            float4 q = qp4[r * 64 + u4];   // uniform broadcast
            acc[r] = fmaf(vv.x, tanh_approx(q.x + k4.x),
                     fmaf(vv.y, tanh_approx(q.y + k4.y),
                     fmaf(vv.z, tanh_approx(q.z + k4.z),
                     fmaf(vv.w, tanh_approx(q.w + k4.w), acc[r]))));
        }
    }
#pragma unroll
    for (int r = 0; r < TQ; r++) part[w][r][l] = acc[r];
    __syncthreads();

    {   // 256 threads = 8 rows x 32 lanes: reduce over 8 warps and store
        const int r = tid >> 5, ll = tid & 31;
        float s = 0.f;
#pragma unroll
        for (int ww = 0; ww < 8; ww++) s += part[ww][r][ll];
        g_sc[(size_t)(b * QQ + q0 + r) * KK + k0 + ll] = s;
    }
}

// ---------------------------------------------------------------------------
// Softmax + output, d-split: block = (qtile, b, d-half). 128 threads.
// ---------------------------------------------------------------------------
__global__ __launch_bounds__(128) void softout_kernel(const float* __restrict__ value,
                                                      const int* __restrict__ valid_len,
                                                      float* __restrict__ out) {
    __shared__ float sc[TQO * KK];         // 8KB normalized attn

    const int tid = threadIdx.x;
    const int b   = blockIdx.y;
    const int q0  = blockIdx.x * TQO;
    const int dh  = blockIdx.z * 128;
    const int vl  = __ldg(&valid_len[b]);
    const int w = tid >> 5, l = tid & 31;

    {   // warp w: softmax of row w
        const float* row = g_sc + (size_t)(b * QQ + q0 + w) * KK;
        float vals[16];
        float m = -3.0e38f;
#pragma unroll
        for (int i = 0; i < 16; i++) {
            int k = l + 32 * i;
            float s = (k < vl) ? __ldg(&row[k]) : -1e6f;
            vals[i] = s;
            m = fmaxf(m, s);
        }
#pragma unroll
        for (int off = 16; off; off >>= 1) m = fmaxf(m, __shfl_xor_sync(0xffffffffu, m, off));
        float ssum = 0.0f;
#pragma unroll
        for (int i = 0; i < 16; i++) {
            float e = __expf(vals[i] - m);
            vals[i] = e;
            ssum += e;
        }
#pragma unroll
        for (int off = 16; off; off >>= 1) ssum += __shfl_xor_sync(0xffffffffu, ssum, off);
        float inv = 1.0f / ssum;
#pragma unroll
        for (int i = 0; i < 16; i++) sc[w * KK + l + 32 * i] = vals[i] * inv;
    }
    __syncthreads();

    const int d = dh + tid;
    float oacc[TQO];
#pragma unroll
    for (int q = 0; q < TQO; q++) oacc[q] = 0.0f;
    const float* vb = value + (size_t)b * KK * DD;
    const int kend = (vl + 3) & ~3;
#pragma unroll 2
    for (int k = 0; k < kend; k += 4) {
        float v0 = vb[(k + 0) * DD + d];
        float v1 = vb[(k + 1) * DD + d];
        float v2 = vb[(k + 2) * DD + d];
        float v3 = vb[(k + 3) * DD + d];
#pragma unroll
        for (int q = 0; q < TQO; q++) {
            float4 a = *(const float4*)&sc[q * KK + k];
            oacc[q] = fmaf(a.x, v0, fmaf(a.y, v1, fmaf(a.z, v2, fmaf(a.w, v3, oacc[q]))));
        }
    }
    float* ob = out + (size_t)(b * QQ + q0) * DD + d;
#pragma unroll
    for (int q = 0; q < TQO; q++) ob[q * DD] = oacc[q];
}

// ---------------------------------------------------------------------------
// Launch
// ---------------------------------------------------------------------------
extern "C" void kernel_launch(void* const* d_in, const int* in_sizes, int n_in,
                              void* d_out, int out_size) {
    const float* query     = (const float*)d_in[0];
    const float* key       = (const float*)d_in[1];
    const float* value     = (const float*)d_in[2];
    const int*   valid_len = (const int*)d_in[3];
    const float* Wq        = (const float*)d_in[4];
    const float* Wk        = (const float*)d_in[5];
    const float* v_w       = (const float*)d_in[6];
    float* out = (float*)d_out;

    proj_gemm<<<dim3(UU / 64, (BB * QQ + BB * KK) / 32), 128>>>(query, key, Wq, Wk);
    score_kernel<<<dim3(KK / KC, QQ / TQ, BB), 256>>>(valid_len, v_w);
    softout_kernel<<<dim3(QQ / TQO, BB, DD / 128), 128>>>(value, valid_len, out);
}

// round 17
// speedup vs baseline: 1.2387x; 1.1530x over previous
#include <cuda_runtime.h>
#include <cuda_bf16.h>
#include <cstdint>

// Problem constants
#define BB 8
#define QQ 128
#define KK 512
#define DD 256
#define UU 256
#define TQ 8               // q rows per score block
#define KC 32              // k rows per score block
#define TQO 4              // q rows per softout block

// Scratch (static device arrays: no allocation)
__device__ float g_qp[BB * QQ * UU];   // 1 MB
__device__ float g_kp[BB * KK * UU];   // 4 MB
__device__ float g_sc[BB * QQ * KK];   // 2 MB raw scores

__device__ __forceinline__ float tanh_approx(float x) {
    float y;
    asm("tanh.approx.f32 %0, %1;" : "=f"(y) : "f"(x));
    return y;
}

__device__ __forceinline__ uint32_t f2tf32(float x) {
    uint32_t r;
    asm("cvt.rna.tf32.f32 %0, %1;" : "=r"(r) : "f"(x));
    return r;
}

__device__ __forceinline__ void mma_tf32(float* c,
                                         uint32_t a0, uint32_t a1, uint32_t a2, uint32_t a3,
                                         uint32_t b0, uint32_t b1) {
    asm volatile("mma.sync.aligned.m16n8k8.row.col.f32.tf32.tf32.f32 "
                 "{%0,%1,%2,%3}, {%4,%5,%6,%7}, {%8,%9}, {%0,%1,%2,%3};"
                 : "+f"(c[0]), "+f"(c[1]), "+f"(c[2]), "+f"(c[3])
                 : "r"(a0), "r"(a1), "r"(a2), "r"(a3), "r"(b0), "r"(b1));
}

__device__ __forceinline__ void cp_async16(uint32_t smem, const void* g) {
    asm volatile("cp.async.cg.shared.global [%0], [%1], 16;\n" :: "r"(smem), "l"(g));
}
__device__ __forceinline__ void cp_commit() { asm volatile("cp.async.commit_group;\n"); }
template <int N>
__device__ __forceinline__ void cp_wait() { asm volatile("cp.async.wait_group %0;\n" :: "n"(N)); }

// ---------------------------------------------------------------------------
// TF32 tensor-core projection GEMM.
// rows [0,1024) = query@Wq -> g_qp ; rows [1024,5120) = key@Wk -> g_kp.
// BM=64, BN=32, BK=16, 128 threads (4 warps, warp tile 16m x 32n).
// Operands rounded to tf32 (cvt.rna) at SMEM store.
// A tile pitch 20 floats / W tile pitch 40: conflict-free fragment loads.
// Grid = 8 n-tiles x 80 m-tiles = 640 blocks (uniform, ~4.3/SM).
// ---------------------------------------------------------------------------
__global__ __launch_bounds__(128) void proj_gemm(const float* __restrict__ query,
                                                 const float* __restrict__ key,
                                                 const float* __restrict__ Wq,
                                                 const float* __restrict__ Wk) {
    __shared__ uint32_t Asu[64 * 20];   // 5.0KB  A tile [64 rows][16 k] pitch 20
    __shared__ uint32_t Wsu[16 * 40];   // 2.5KB  W tile [16 k][32 n] pitch 40

    const int tid = threadIdx.x;
    const int m0  = blockIdx.y * 64;
    const int n0  = blockIdx.x * 32;

    const float* A; const float* W; float* C;
    if (m0 < BB * QQ) { A = query + (size_t)m0 * DD;             W = Wq; C = g_qp + (size_t)m0 * UU; }
    else              { A = key   + (size_t)(m0 - BB * QQ) * DD; W = Wk; C = g_kp + (size_t)(m0 - BB * QQ) * UU; }

    const int w    = tid >> 5;
    const int lane = tid & 31;
    const int g    = lane >> 2;       // group id (0..7)
    const int tig  = lane & 3;        // thread in group

    // global load indices
    const int arow = tid >> 2;        // 0..31 (and +32)
    const int akq  = (tid & 3) * 4;   // k col base (0,4,8,12)
    const int wk   = tid >> 4;        // 0..7 (and +8)
    const int wnq  = (tid & 15) * 4;  // n col base... (only 0..28 valid for BN=32)

    // W tile is 16x32 floats = 128 float4; 128 threads -> 1 each:
    // thread: k = tid>>3 (0..15), nq = (tid&7)*4
    const int wk1  = tid >> 3;
    const int wnq1 = (tid & 7) * 4;

    float acc[4][4];
#pragma unroll
    for (int i = 0; i < 4; i++)
#pragma unroll
        for (int j = 0; j < 4; j++) acc[i][j] = 0.0f;

    // preload slab 0
    float4 a0v = *(const float4*)&A[(arow)      * DD + akq];
    float4 a1v = *(const float4*)&A[(arow + 32) * DD + akq];
    float4 w0v = *(const float4*)&W[(wk1) * UU + n0 + wnq1];

    for (int k0 = 0; k0 < DD; k0 += 16) {
        __syncthreads();
        {   // store pre-rounded tf32 operands
            uint32_t* pa = Asu + arow * 20 + akq;
            pa[0] = f2tf32(a0v.x); pa[1] = f2tf32(a0v.y);
            pa[2] = f2tf32(a0v.z); pa[3] = f2tf32(a0v.w);
            uint32_t* pb = Asu + (arow + 32) * 20 + akq;
            pb[0] = f2tf32(a1v.x); pb[1] = f2tf32(a1v.y);
            pb[2] = f2tf32(a1v.z); pb[3] = f2tf32(a1v.w);
            uint32_t* pw = Wsu + wk1 * 40 + wnq1;
            pw[0] = f2tf32(w0v.x); pw[1] = f2tf32(w0v.y);
            pw[2] = f2tf32(w0v.z); pw[3] = f2tf32(w0v.w);
        }
        __syncthreads();
        if (k0 + 16 < DD) {   // prefetch next slab under compute
            a0v = *(const float4*)&A[(arow)      * DD + k0 + 16 + akq];
            a1v = *(const float4*)&A[(arow + 32) * DD + k0 + 16 + akq];
            w0v = *(const float4*)&W[(k0 + 16 + wk1) * UU + n0 + wnq1];
        }
#pragma unroll
        for (int ks = 0; ks < 16; ks += 8) {
            const uint32_t* Ab = Asu + (w * 16) * 20 + ks;
            uint32_t fa0 = Ab[(g)     * 20 + tig];
            uint32_t fa1 = Ab[(g + 8) * 20 + tig];
            uint32_t fa2 = Ab[(g)     * 20 + tig + 4];
            uint32_t fa3 = Ab[(g + 8) * 20 + tig + 4];
#pragma unroll
            for (int nf = 0; nf < 4; nf++) {
                uint32_t fb0 = Wsu[(ks + tig)     * 40 + nf * 8 + g];
                uint32_t fb1 = Wsu[(ks + tig + 4) * 40 + nf * 8 + g];
                mma_tf32(acc[nf], fa0, fa1, fa2, fa3, fb0, fb1);
            }
        }
    }

    // epilogue: c0,c1 -> (row, col..col+1), c2,c3 -> (row+8, same)
    const int row = w * 16 + g;
    const int col = n0 + 2 * tig;
#pragma unroll
    for (int nf = 0; nf < 4; nf++) {
        *(float2*)&C[(size_t)(row)     * UU + col + nf * 8] = make_float2(acc[nf][0], acc[nf][1]);
        *(float2*)&C[(size_t)(row + 8) * UU + col + nf * 8] = make_float2(acc[nf][2], acc[nf][3]);
    }
}

// ---------------------------------------------------------------------------
// Score kernel (R13, f32 tanh): block per (chunk, qtile of 8, b).
// 256 thr; warp w owns u4-range [8w,8w+8); lane l = k-row.
// ---------------------------------------------------------------------------
__global__ __launch_bounds__(256, 4) void score_kernel(const int* __restrict__ valid_len,
                                                       const float* __restrict__ v_w) {
    __shared__ float4 kb[KC * 64];        // 32KB swizzled kp chunk
    __shared__ float  qp_s[TQ * UU];      // 8KB
    __shared__ float  vw_s[UU];           // 1KB
    __shared__ float  part[8][TQ][32];    // 8KB u-partials

    const int b  = blockIdx.z;
    const int vl = __ldg(&valid_len[b]);
    const int k0 = blockIdx.x * KC;
    if (k0 >= vl) return;

    const int tid = threadIdx.x;
    const int q0  = blockIdx.y * TQ;

    {
        const float4* qg = (const float4*)(g_qp + (size_t)(b * QQ + q0) * UU);
        ((float4*)qp_s)[tid]       = qg[tid];
        ((float4*)qp_s)[tid + 256] = qg[tid + 256];
        if (tid < 64) ((float4*)vw_s)[tid] = ((const float4*)v_w)[tid];
    }

    const float4* src = (const float4*)(g_kp + ((size_t)b * KK + k0) * UU);
    const uint32_t kb_base = (uint32_t)__cvta_generic_to_shared(kb);
#pragma unroll
    for (int i = 0; i < 8; i++) {
        int idx = tid + i * 256;
        int rr = idx >> 6, cc = idx & 63;
        cp_async16(kb_base + ((uint32_t)(rr * 64 + (cc ^ (rr & 7))) << 4), src + idx);
    }
    cp_commit();
    cp_wait<0>();
    __syncthreads();

    const int w = tid >> 5, l = tid & 31;
    const float4* kbuf = kb + l * 64;
    const float4* qp4  = (const float4*)qp_s;
    const float4* vw4  = (const float4*)vw_s;
    const int u0  = w * 8;
    const int swl = l & 7;

    float acc[TQ];
#pragma unroll
    for (int r = 0; r < TQ; r++) acc[r] = 0.0f;

#pragma unroll
    for (int j = 0; j < 8; j++) {
        const int u4 = u0 + j;
        float4 k4 = kbuf[u4 ^ swl];        // spread, conflict-free
        float4 vv = vw4[u4];               // uniform broadcast
#pragma unroll
        for (int r = 0; r < TQ; r++) {
            float4 q = qp4[r * 64 + u4];   // uniform broadcast
            acc[r] = fmaf(vv.x, tanh_approx(q.x + k4.x),
                     fmaf(vv.y, tanh_approx(q.y + k4.y),
                     fmaf(vv.z, tanh_approx(q.z + k4.z),
                     fmaf(vv.w, tanh_approx(q.w + k4.w), acc[r]))));
        }
    }
#pragma unroll
    for (int r = 0; r < TQ; r++) part[w][r][l] = acc[r];
    __syncthreads();

    {   // 256 threads = 8 rows x 32 lanes: reduce over 8 warps and store
        const int r = tid >> 5, ll = tid & 31;
        float s = 0.f;
#pragma unroll
        for (int ww = 0; ww < 8; ww++) s += part[ww][r][ll];
        g_sc[(size_t)(b * QQ + q0 + r) * KK + k0 + ll] = s;
    }
}

// ---------------------------------------------------------------------------
// Softmax + output, d-split: block = (qtile, b, d-half). 128 threads.
// ---------------------------------------------------------------------------
__global__ __launch_bounds__(128) void softout_kernel(const float* __restrict__ value,
                                                      const int* __restrict__ valid_len,
                                                      float* __restrict__ out) {
    __shared__ float sc[TQO * KK];         // 8KB normalized attn

    const int tid = threadIdx.x;
    const int b   = blockIdx.y;
    const int q0  = blockIdx.x * TQO;
    const int dh  = blockIdx.z * 128;
    const int vl  = __ldg(&valid_len[b]);
    const int w = tid >> 5, l = tid & 31;

    {   // warp w: softmax of row w
        const float* row = g_sc + (size_t)(b * QQ + q0 + w) * KK;
        float vals[16];
        float m = -3.0e38f;
#pragma unroll
        for (int i = 0; i < 16; i++) {
            int k = l + 32 * i;
            float s = (k < vl) ? __ldg(&row[k]) : -1e6f;
            vals[i] = s;
            m = fmaxf(m, s);
        }
#pragma unroll
        for (int off = 16; off; off >>= 1) m = fmaxf(m, __shfl_xor_sync(0xffffffffu, m, off));
        float ssum = 0.0f;
#pragma unroll
        for (int i = 0; i < 16; i++) {
            float e = __expf(vals[i] - m);
            vals[i] = e;
            ssum += e;
        }
#pragma unroll
        for (int off = 16; off; off >>= 1) ssum += __shfl_xor_sync(0xffffffffu, ssum, off);
        float inv = 1.0f / ssum;
#pragma unroll
        for (int i = 0; i < 16; i++) sc[w * KK + l + 32 * i] = vals[i] * inv;
    }
    __syncthreads();

    const int d = dh + tid;
    float oacc[TQO];
#pragma unroll
    for (int q = 0; q < TQO; q++) oacc[q] = 0.0f;
    const float* vb = value + (size_t)b * KK * DD;
    const int kend = (vl + 3) & ~3;
#pragma unroll 2
    for (int k = 0; k < kend; k += 4) {
        float v0 = vb[(k + 0) * DD + d];
        float v1 = vb[(k + 1) * DD + d];
        float v2 = vb[(k + 2) * DD + d];
        float v3 = vb[(k + 3) * DD + d];
#pragma unroll
        for (int q = 0; q < TQO; q++) {
            float4 a = *(const float4*)&sc[q * KK + k];
            oacc[q] = fmaf(a.x, v0, fmaf(a.y, v1, fmaf(a.z, v2, fmaf(a.w, v3, oacc[q]))));
        }
    }
    float* ob = out + (size_t)(b * QQ + q0) * DD + d;
#pragma unroll
    for (int q = 0; q < TQO; q++) ob[q * DD] = oacc[q];
}

// ---------------------------------------------------------------------------
// Launch
// ---------------------------------------------------------------------------
extern "C" void kernel_launch(void* const* d_in, const int* in_sizes, int n_in,
                              void* d_out, int out_size) {
    const float* query     = (const float*)d_in[0];
    const float* key       = (const float*)d_in[1];
    const float* value     = (const float*)d_in[2];
    const int*   valid_len = (const int*)d_in[3];
    const float* Wq        = (const float*)d_in[4];
    const float* Wk        = (const float*)d_in[5];
    const float* v_w       = (const float*)d_in[6];
    float* out = (float*)d_out;

    proj_gemm<<<dim3(UU / 32, (BB * QQ + BB * KK) / 64), 128>>>(query, key, Wq, Wk);
    score_kernel<<<dim3(KK / KC, QQ / TQ, BB), 256>>>(valid_len, v_w);
    softout_kernel<<<dim3(QQ / TQO, BB, DD / 128), 128>>>(value, valid_len, out);
}